// round 2
// baseline (speedup 1.0000x reference)
#include <cuda_runtime.h>
#include <math.h>

#define NB 8
#define LSEQ 2048
#define CDIM 512
#define HDIM 512
#define CHALF 256

// ---------------- scratch (device globals: allocation-guard safe) ----------
__device__ float g_xt  [(size_t)NB * LSEQ * HDIM];
__device__ float g_xph [(size_t)NB * LSEQ * HDIM];
__device__ float g_xpsi[(size_t)NB * LSEQ * HDIM];
__device__ float g_S   [(size_t)NB * LSEQ * LSEQ];   // 134 MB attention matrix
__device__ float g_xadd[(size_t)NB * LSEQ * HDIM];
__device__ float g_h1  [(size_t)NB * LSEQ * CHALF];

// ---------------- generic fp32 tiled GEMM ---------------------------------
// C[M,N] = A[M,K] @ op(B) (+bias) with optional epilogue.
// TRANSB: B is [N,K] row-major (so C = A @ B^T).
// EPI: 0 = (+bias), 1 = leaky_relu(+bias, 0.2), 2 = tanh(+bias) + residual
// Batched via blockIdx.z with element strides sA/sB/sC (res uses sC).
template <bool TRANSB, int EPI>
__global__ void __launch_bounds__(256)
gemm_k(const float* __restrict__ A, const float* __restrict__ B,
       const float* __restrict__ bias, const float* __restrict__ res,
       float* __restrict__ C,
       int M, int N, int K, long sA, long sB, long sC)
{
    const int BM = 128, BN = 128, BK = 16;
    __shared__ float As[BK][BM];
    __shared__ float Bs[BK][BN];

    long bz = blockIdx.z;
    A += bz * sA;
    B += bz * sB;
    C += bz * sC;
    const float* Rres = (EPI == 2) ? (res + bz * sC) : res;

    int m0 = blockIdx.y * BM;
    int n0 = blockIdx.x * BN;
    int tid = threadIdx.x;
    int tx = tid & 15;        // 0..15 -> 8 cols each
    int ty = tid >> 4;        // 0..15 -> 8 rows each

    float acc[8][8];
#pragma unroll
    for (int i = 0; i < 8; i++)
#pragma unroll
        for (int j = 0; j < 8; j++) acc[i][j] = 0.f;

    for (int k0 = 0; k0 < K; k0 += BK) {
        // --- load A tile (transposed into As[k][m]) ---
        {
            int r  = tid >> 2;          // 0..63
            int kc = (tid & 3) * 4;
#pragma unroll
            for (int h = 0; h < 2; h++) {
                int row = r + h * 64;
                float4 v = *(const float4*)&A[(long)(m0 + row) * K + k0 + kc];
                As[kc + 0][row] = v.x;
                As[kc + 1][row] = v.y;
                As[kc + 2][row] = v.z;
                As[kc + 3][row] = v.w;
            }
        }
        // --- load B tile ---
        if (!TRANSB) {
            int r = tid >> 5;           // 0..7
            int c = (tid & 31) * 4;
#pragma unroll
            for (int h = 0; h < 2; h++) {
                float4 v = *(const float4*)&B[(long)(k0 + r + h * 8) * N + n0 + c];
                *(float4*)&Bs[r + h * 8][c] = v;
            }
        } else {
            int nn = tid >> 2;          // 0..63
            int kc = (tid & 3) * 4;
#pragma unroll
            for (int h = 0; h < 2; h++) {
                int n = nn + h * 64;
                float4 v = *(const float4*)&B[(long)(n0 + n) * K + k0 + kc];
                Bs[kc + 0][n] = v.x;
                Bs[kc + 1][n] = v.y;
                Bs[kc + 2][n] = v.z;
                Bs[kc + 3][n] = v.w;
            }
        }
        __syncthreads();

#pragma unroll
        for (int k = 0; k < BK; k++) {
            float a[8], b[8];
            *(float4*)&a[0] = *(const float4*)&As[k][ty * 8];
            *(float4*)&a[4] = *(const float4*)&As[k][ty * 8 + 4];
            *(float4*)&b[0] = *(const float4*)&Bs[k][tx * 8];
            *(float4*)&b[4] = *(const float4*)&Bs[k][tx * 8 + 4];
#pragma unroll
            for (int i = 0; i < 8; i++)
#pragma unroll
                for (int j = 0; j < 8; j++)
                    acc[i][j] += a[i] * b[j];
        }
        __syncthreads();
    }

    // --- epilogue ---
#pragma unroll
    for (int i = 0; i < 8; i++) {
        int row = m0 + ty * 8 + i;
#pragma unroll
        for (int j = 0; j < 8; j += 4) {
            int col = n0 + tx * 8 + j;
            float4 o;
            float* po = (float*)&o;
#pragma unroll
            for (int u = 0; u < 4; u++) {
                float v = acc[i][j + u];
                if (bias) v += bias[col + u];
                if (EPI == 1) v = fmaxf(v, 0.2f * v);            // leaky_relu(0.2)
                if (EPI == 2) v = tanhf(v) + Rres[(long)row * N + col + u];
                po[u] = v;
            }
            *(float4*)&C[(long)row * N + col] = o;
        }
    }
}

// ---------------- row softmax over last dim --------------------------------
__global__ void __launch_bounds__(256)
softmax_rows(float* __restrict__ S, int L)
{
    long base = (long)blockIdx.x * L;
    int tid = threadIdx.x;
    __shared__ float red[256];

    float m = -1e30f;
    for (int i = tid; i < L; i += 256) m = fmaxf(m, S[base + i]);
    red[tid] = m;
    __syncthreads();
    for (int s = 128; s > 0; s >>= 1) {
        if (tid < s) red[tid] = fmaxf(red[tid], red[tid + s]);
        __syncthreads();
    }
    m = red[0];
    __syncthreads();

    float sum = 0.f;
    for (int i = tid; i < L; i += 256) {
        float e = expf(S[base + i] - m);
        S[base + i] = e;
        sum += e;
    }
    red[tid] = sum;
    __syncthreads();
    for (int s = 128; s > 0; s >>= 1) {
        if (tid < s) red[tid] += red[tid + s];
        __syncthreads();
    }
    float inv = 1.f / red[0];
    __syncthreads();

    for (int i = tid; i < L; i += 256) S[base + i] *= inv;
}

// ---------------- launch ----------------------------------------------------
extern "C" void kernel_launch(void* const* d_in, const int* in_sizes, int n_in,
                              void* d_out, int out_size)
{
    const float* x    = (const float*)d_in[0];
    const float* thw  = (const float*)d_in[1];
    const float* thb  = (const float*)d_in[2];
    const float* phw  = (const float*)d_in[3];
    const float* phb  = (const float*)d_in[4];
    const float* psw  = (const float*)d_in[5];
    const float* psb  = (const float*)d_in[6];
    const float* r1w  = (const float*)d_in[7];
    const float* r1b  = (const float*)d_in[8];
    const float* r2w  = (const float*)d_in[9];
    const float* r2b  = (const float*)d_in[10];
    float* out = (float*)d_out;

    float *p_xt, *p_xph, *p_xpsi, *p_S, *p_xadd, *p_h1;
    cudaGetSymbolAddress((void**)&p_xt,   g_xt);
    cudaGetSymbolAddress((void**)&p_xph,  g_xph);
    cudaGetSymbolAddress((void**)&p_xpsi, g_xpsi);
    cudaGetSymbolAddress((void**)&p_S,    g_S);
    cudaGetSymbolAddress((void**)&p_xadd, g_xadd);
    cudaGetSymbolAddress((void**)&p_h1,   g_h1);

    const int M  = NB * LSEQ;                    // 16384
    const long sLH = (long)LSEQ * HDIM;          // 2048*512
    const long sLL = (long)LSEQ * LSEQ;          // 2048*2048

    // 1) three projections: [16384,512] @ [512,512] + bias
    {
        dim3 g(HDIM / 128, M / 128, 1);
        gemm_k<false, 0><<<g, 256>>>(x, thw, thb, nullptr, p_xt,   M, HDIM, CDIM, 0, 0, 0);
        gemm_k<false, 0><<<g, 256>>>(x, phw, phb, nullptr, p_xph,  M, HDIM, CDIM, 0, 0, 0);
        gemm_k<false, 0><<<g, 256>>>(x, psw, psb, nullptr, p_xpsi, M, HDIM, CDIM, 0, 0, 0);
    }

    // 2) logits: S[b] = x_ph[b] @ x_t[b]^T   [2048,2048] per batch
    {
        dim3 g(LSEQ / 128, LSEQ / 128, NB);
        gemm_k<true, 0><<<g, 256>>>(p_xph, p_xt, nullptr, nullptr, p_S,
                                    LSEQ, LSEQ, HDIM, sLH, sLH, sLL);
    }

    // 3) softmax rows
    softmax_rows<<<NB * LSEQ, 256>>>(p_S, LSEQ);

    // 4) x_add[b] = S[b] @ x_psi[b]   [2048,512]
    {
        dim3 g(HDIM / 128, LSEQ / 128, NB);
        gemm_k<false, 0><<<g, 256>>>(p_S, p_xpsi, nullptr, nullptr, p_xadd,
                                     LSEQ, HDIM, LSEQ, sLL, sLH, sLH);
    }

    // 5) h1 = leaky_relu(x_add @ r1_w + r1_b)   [16384,256]
    {
        dim3 g(CHALF / 128, M / 128, 1);
        gemm_k<false, 1><<<g, 256>>>(p_xadd, r1w, r1b, nullptr, p_h1,
                                     M, CHALF, HDIM, 0, 0, 0);
    }

    // 6) out = x + tanh(h1 @ r2_w + r2_b)   [16384,512]
    {
        dim3 g(CDIM / 128, M / 128, 1);
        gemm_k<false, 2><<<g, 256>>>(p_h1, r2w, r2b, x, out,
                                     M, CDIM, CHALF, 0, 0, 0);
    }
}

// round 5
// speedup vs baseline: 2.9915x; 2.9915x over previous
#include <cuda_runtime.h>
#include <math.h>
#include <stdint.h>

#define NB 8
#define LSEQ 2048
#define CDIM 512
#define HDIM 512
#define CHALF 256

// ---------------- scratch (device globals: allocation-guard safe) ----------
__device__ float g_xt  [(size_t)NB * LSEQ * HDIM];
__device__ float g_xph [(size_t)NB * LSEQ * HDIM];
__device__ float g_xpsi[(size_t)NB * LSEQ * HDIM];
__device__ float g_S   [(size_t)NB * LSEQ * LSEQ];
__device__ float g_xadd[(size_t)NB * LSEQ * HDIM];
__device__ float g_h1  [(size_t)NB * LSEQ * CHALF];
__device__ float g_xr  [(size_t)NB * LSEQ * CDIM];   // tf32-rounded x
__device__ float g_wth [CDIM * HDIM];
__device__ float g_wph [CDIM * HDIM];
__device__ float g_wps [CDIM * HDIM];
__device__ float g_wr1 [HDIM * CHALF];
__device__ float g_wr2 [CHALF * CDIM];

// ---------------- helpers ---------------------------------------------------
__device__ __forceinline__ float tf32r(float x) {
    uint32_t r;
    asm("cvt.rna.tf32.f32 %0, %1;" : "=r"(r) : "f"(x));
    return __uint_as_float(r);
}

__device__ __forceinline__ void cp16(void* dst_smem, const void* src_gmem) {
    uint32_t d = (uint32_t)__cvta_generic_to_shared(dst_smem);
    asm volatile("cp.async.cg.shared.global [%0], [%1], 16;\n" :: "r"(d), "l"(src_gmem) : "memory");
}
#define CP_COMMIT() asm volatile("cp.async.commit_group;\n" ::: "memory")
#define CP_WAIT1()  asm volatile("cp.async.wait_group 1;\n" ::: "memory")
#define CP_WAIT0()  asm volatile("cp.async.wait_group 0;\n" ::: "memory")

__device__ __forceinline__ void mma_tf32(float* c, const uint32_t* a, const uint32_t* b) {
    asm volatile(
        "mma.sync.aligned.m16n8k8.row.col.f32.tf32.tf32.f32 "
        "{%0,%1,%2,%3}, {%4,%5,%6,%7}, {%8,%9}, {%0,%1,%2,%3};\n"
        : "+f"(c[0]), "+f"(c[1]), "+f"(c[2]), "+f"(c[3])
        : "r"(a[0]), "r"(a[1]), "r"(a[2]), "r"(a[3]), "r"(b[0]), "r"(b[1]));
}

// ---------------- tensor-core tf32 GEMM -------------------------------------
// C[M,N] = A[M,K] @ op(B) (+bias). TRANSB: B is [N,K] (C = A@B^T).
// EPI: 0 = bias, 1 = leaky_relu(0.2), 2 = tanh + residual
// ROUND: round outputs to tf32 (rna) for the next GEMM's consumption.
template <bool TRANSB, int EPI, bool ROUND>
__global__ void __launch_bounds__(256)
gemm_tc(const float* __restrict__ A, const float* __restrict__ B,
        const float* __restrict__ bias, const float* __restrict__ res,
        float* __restrict__ C,
        int M, int N, int K, long sA, long sB, long sC)
{
    constexpr int AS = 20;                       // A row stride (16 + 4 pad)
    constexpr int BS = TRANSB ? 20 : 136;        // B layout stride
    constexpr int BSZ = TRANSB ? 128 * 20 : 16 * 136;
    __shared__ __align__(16) float As[2][128 * AS];
    __shared__ __align__(16) float Bs[2][BSZ];

    long bz = blockIdx.z;
    A += bz * sA;
    B += bz * sB;
    C += bz * sC;
    const float* Rres = (EPI == 2) ? (res + bz * sC) : res;

    const int m0 = blockIdx.y * 128;
    const int n0 = blockIdx.x * 128;
    const int tid = threadIdx.x;
    const int warp = tid >> 5, lane = tid & 31;
    const int wm = warp >> 2, wn = warp & 3;     // 2x4 warp grid
    const int m_off = wm * 64, n_off = wn * 32;
    const int gid = lane >> 2, tig = lane & 3;

    float acc[4][4][4];
#pragma unroll
    for (int i = 0; i < 4; i++)
#pragma unroll
        for (int j = 0; j < 4; j++)
#pragma unroll
            for (int u = 0; u < 4; u++) acc[i][j][u] = 0.f;

    const int KT = K >> 4;

    // ---- async tile loaders (512 16B chunks each; 2 per thread) ----
    auto loadA = [&](int kt, int buf) {
#pragma unroll
        for (int s = 0; s < 2; s++) {
            int c = tid + s * 256;
            int row = c >> 2, seg = c & 3;
            cp16(&As[buf][row * AS + seg * 4],
                 &A[(long)(m0 + row) * K + kt * 16 + seg * 4]);
        }
    };
    auto loadB = [&](int kt, int buf) {
        if (TRANSB) {
#pragma unroll
            for (int s = 0; s < 2; s++) {
                int c = tid + s * 256;
                int row = c >> 2, seg = c & 3;
                cp16(&Bs[buf][row * BS + seg * 4],
                     &B[(long)(n0 + row) * K + kt * 16 + seg * 4]);
            }
        } else {
#pragma unroll
            for (int s = 0; s < 2; s++) {
                int c = tid + s * 256;
                int row = c >> 5, seg = c & 31;
                cp16(&Bs[buf][row * BS + seg * 4],
                     &B[(long)(kt * 16 + row) * N + n0 + seg * 4]);
            }
        }
    };

    loadA(0, 0); loadB(0, 0); CP_COMMIT();

    for (int kt = 0; kt < KT; kt++) {
        const int buf = kt & 1;
        if (kt + 1 < KT) {
            loadA(kt + 1, buf ^ 1); loadB(kt + 1, buf ^ 1); CP_COMMIT();
            CP_WAIT1();
        } else {
            CP_WAIT0();
        }
        __syncthreads();

        const float* As_ = As[buf];
        const float* Bs_ = Bs[buf];
#pragma unroll
        for (int kk = 0; kk < 16; kk += 8) {
            uint32_t a[4][4], b[4][2];
#pragma unroll
            for (int mi = 0; mi < 4; mi++) {
                int r = m_off + mi * 16 + gid;
                a[mi][0] = __float_as_uint(As_[r * AS + kk + tig]);
                a[mi][1] = __float_as_uint(As_[(r + 8) * AS + kk + tig]);
                a[mi][2] = __float_as_uint(As_[r * AS + kk + tig + 4]);
                a[mi][3] = __float_as_uint(As_[(r + 8) * AS + kk + tig + 4]);
            }
#pragma unroll
            for (int ni = 0; ni < 4; ni++) {
                if (TRANSB) {
                    int n = n_off + ni * 8 + gid;
                    b[ni][0] = __float_as_uint(Bs_[n * 20 + kk + tig]);
                    b[ni][1] = __float_as_uint(Bs_[n * 20 + kk + tig + 4]);
                } else {
                    int n = n_off + ni * 8 + gid;
                    b[ni][0] = __float_as_uint(Bs_[(kk + tig) * 136 + n]);
                    b[ni][1] = __float_as_uint(Bs_[(kk + tig + 4) * 136 + n]);
                }
            }
#pragma unroll
            for (int mi = 0; mi < 4; mi++)
#pragma unroll
                for (int ni = 0; ni < 4; ni++)
                    mma_tf32(acc[mi][ni], a[mi], b[ni]);
        }
        __syncthreads();
    }

    // ---- epilogue ----
#pragma unroll
    for (int mi = 0; mi < 4; mi++) {
#pragma unroll
        for (int ni = 0; ni < 4; ni++) {
            int col = n0 + n_off + ni * 8 + tig * 2;
#pragma unroll
            for (int h = 0; h < 2; h++) {               // h=0: rows +0, h=1: rows +8
                int row = m0 + m_off + mi * 16 + gid + h * 8;
                float v0 = acc[mi][ni][h * 2 + 0];
                float v1 = acc[mi][ni][h * 2 + 1];
                if (bias) { v0 += bias[col]; v1 += bias[col + 1]; }
                if (EPI == 1) { v0 = fmaxf(v0, 0.2f * v0); v1 = fmaxf(v1, 0.2f * v1); }
                if (EPI == 2) {
                    v0 = tanhf(v0) + Rres[(long)row * N + col];
                    v1 = tanhf(v1) + Rres[(long)row * N + col + 1];
                }
                if (ROUND) { v0 = tf32r(v0); v1 = tf32r(v1); }
                *(float2*)&C[(long)row * N + col] = make_float2(v0, v1);
            }
        }
    }
}

// ---------------- one-pass register-resident softmax ------------------------
// Row of 2048 per block; 256 threads x 8 floats. Rounds output to tf32.
__global__ void __launch_bounds__(256)
softmax_rows(float* __restrict__ S)
{
    long base = (long)blockIdx.x * LSEQ;
    int tid = threadIdx.x;
    float4* S4 = (float4*)(S + base);
    __shared__ float red[256];

    float4 v0 = S4[tid];
    float4 v1 = S4[tid + 256];
    float m = fmaxf(fmaxf(fmaxf(v0.x, v0.y), fmaxf(v0.z, v0.w)),
                    fmaxf(fmaxf(v1.x, v1.y), fmaxf(v1.z, v1.w)));
    red[tid] = m;
    __syncthreads();
    for (int s = 128; s > 0; s >>= 1) {
        if (tid < s) red[tid] = fmaxf(red[tid], red[tid + s]);
        __syncthreads();
    }
    m = red[0];
    __syncthreads();

    v0.x = __expf(v0.x - m); v0.y = __expf(v0.y - m);
    v0.z = __expf(v0.z - m); v0.w = __expf(v0.w - m);
    v1.x = __expf(v1.x - m); v1.y = __expf(v1.y - m);
    v1.z = __expf(v1.z - m); v1.w = __expf(v1.w - m);
    float sum = (v0.x + v0.y + v0.z + v0.w) + (v1.x + v1.y + v1.z + v1.w);
    red[tid] = sum;
    __syncthreads();
    for (int s = 128; s > 0; s >>= 1) {
        if (tid < s) red[tid] += red[tid + s];
        __syncthreads();
    }
    float inv = 1.f / red[0];

    v0.x = tf32r(v0.x * inv); v0.y = tf32r(v0.y * inv);
    v0.z = tf32r(v0.z * inv); v0.w = tf32r(v0.w * inv);
    v1.x = tf32r(v1.x * inv); v1.y = tf32r(v1.y * inv);
    v1.z = tf32r(v1.z * inv); v1.w = tf32r(v1.w * inv);
    S4[tid] = v0;
    S4[tid + 256] = v1;
}

// ---------------- tf32 rounding pass ----------------------------------------
__global__ void __launch_bounds__(256)
round_k(const float* __restrict__ in, float* __restrict__ out, int n4)
{
    int i = blockIdx.x * 256 + threadIdx.x;
    if (i < n4) {
        float4 v = ((const float4*)in)[i];
        v.x = tf32r(v.x); v.y = tf32r(v.y); v.z = tf32r(v.z); v.w = tf32r(v.w);
        ((float4*)out)[i] = v;
    }
}

// ---------------- launch ----------------------------------------------------
extern "C" void kernel_launch(void* const* d_in, const int* in_sizes, int n_in,
                              void* d_out, int out_size)
{
    const float* x    = (const float*)d_in[0];
    const float* thw  = (const float*)d_in[1];
    const float* thb  = (const float*)d_in[2];
    const float* phw  = (const float*)d_in[3];
    const float* phb  = (const float*)d_in[4];
    const float* psw  = (const float*)d_in[5];
    const float* psb  = (const float*)d_in[6];
    const float* r1w  = (const float*)d_in[7];
    const float* r1b  = (const float*)d_in[8];
    const float* r2w  = (const float*)d_in[9];
    const float* r2b  = (const float*)d_in[10];
    float* out = (float*)d_out;

    float *p_xt, *p_xph, *p_xpsi, *p_S, *p_xadd, *p_h1, *p_xr;
    float *p_wth, *p_wph, *p_wps, *p_wr1, *p_wr2;
    cudaGetSymbolAddress((void**)&p_xt,   g_xt);
    cudaGetSymbolAddress((void**)&p_xph,  g_xph);
    cudaGetSymbolAddress((void**)&p_xpsi, g_xpsi);
    cudaGetSymbolAddress((void**)&p_S,    g_S);
    cudaGetSymbolAddress((void**)&p_xadd, g_xadd);
    cudaGetSymbolAddress((void**)&p_h1,   g_h1);
    cudaGetSymbolAddress((void**)&p_xr,   g_xr);
    cudaGetSymbolAddress((void**)&p_wth,  g_wth);
    cudaGetSymbolAddress((void**)&p_wph,  g_wph);
    cudaGetSymbolAddress((void**)&p_wps,  g_wps);
    cudaGetSymbolAddress((void**)&p_wr1,  g_wr1);
    cudaGetSymbolAddress((void**)&p_wr2,  g_wr2);

    const int M = NB * LSEQ;                     // 16384
    const long sLH = (long)LSEQ * HDIM;
    const long sLL = (long)LSEQ * LSEQ;

    // 0) round GEMM operands to tf32 once (rna)
    {
        int n4;
        n4 = M * CDIM / 4;          round_k<<<(n4 + 255) / 256, 256>>>(x,   p_xr,  n4);
        n4 = CDIM * HDIM / 4;       round_k<<<(n4 + 255) / 256, 256>>>(thw, p_wth, n4);
        round_k<<<(n4 + 255) / 256, 256>>>(phw, p_wph, n4);
        round_k<<<(n4 + 255) / 256, 256>>>(psw, p_wps, n4);
        n4 = HDIM * CHALF / 4;      round_k<<<(n4 + 255) / 256, 256>>>(r1w, p_wr1, n4);
        n4 = CHALF * CDIM / 4;      round_k<<<(n4 + 255) / 256, 256>>>(r2w, p_wr2, n4);
    }

    // 1) projections (outputs tf32-rounded for the attention GEMMs)
    {
        dim3 g(HDIM / 128, M / 128, 1);
        gemm_tc<false, 0, true><<<g, 256>>>(p_xr, p_wth, thb, nullptr, p_xt,   M, HDIM, CDIM, 0, 0, 0);
        gemm_tc<false, 0, true><<<g, 256>>>(p_xr, p_wph, phb, nullptr, p_xph,  M, HDIM, CDIM, 0, 0, 0);
        gemm_tc<false, 0, true><<<g, 256>>>(p_xr, p_wps, psb, nullptr, p_xpsi, M, HDIM, CDIM, 0, 0, 0);
    }

    // 2) logits: S[b] = x_ph[b] @ x_t[b]^T
    {
        dim3 g(LSEQ / 128, LSEQ / 128, NB);
        gemm_tc<true, 0, false><<<g, 256>>>(p_xph, p_xt, nullptr, nullptr, p_S,
                                            LSEQ, LSEQ, HDIM, sLH, sLH, sLL);
    }

    // 3) softmax (rounds attn to tf32)
    softmax_rows<<<NB * LSEQ, 256>>>(p_S);

    // 4) x_add[b] = S[b] @ x_psi[b]
    {
        dim3 g(HDIM / 128, LSEQ / 128, NB);
        gemm_tc<false, 0, true><<<g, 256>>>(p_S, p_xpsi, nullptr, nullptr, p_xadd,
                                            LSEQ, HDIM, LSEQ, sLL, sLH, sLH);
    }

    // 5) h1 = leaky_relu(x_add @ r1_w + r1_b)
    {
        dim3 g(CHALF / 128, M / 128, 1);
        gemm_tc<false, 1, true><<<g, 256>>>(p_xadd, p_wr1, r1b, nullptr, p_h1,
                                            M, CHALF, HDIM, 0, 0, 0);
    }

    // 6) out = x + tanh(h1 @ r2_w + r2_b)   (original x as residual)
    {
        dim3 g(CDIM / 128, M / 128, 1);
        gemm_tc<false, 2, false><<<g, 256>>>(p_h1, p_wr2, r2b, x, out,
                                             M, CDIM, CHALF, 0, 0, 0);
    }
}

// round 9
// speedup vs baseline: 6.4726x; 2.1637x over previous
#include <cuda_runtime.h>
#include <cuda_bf16.h>
#include <math.h>
#include <stdint.h>

#define NB 8
#define LSEQ 2048
#define CDIM 512
#define HDIM 512
#define CHALF 256
typedef __nv_bfloat16 bf16;

#if defined(__CUDA_ARCH__) && defined(__CUDA_ARCH_FEAT_SM103_ALL)
#define TC05 1
#else
#define TC05 0
#endif

// ---------------- scratch (device globals: allocation-guard safe) ----------
__device__ __align__(1024) bf16 g_xb   [(size_t)NB * LSEQ * CDIM];
__device__ __align__(1024) bf16 g_wthT [HDIM * CDIM];
__device__ __align__(1024) bf16 g_wphT [HDIM * CDIM];
__device__ __align__(1024) bf16 g_wpsT [HDIM * CDIM];
__device__ __align__(1024) bf16 g_wr1T [CHALF * HDIM];
__device__ __align__(1024) bf16 g_wr2T [CDIM * CHALF];
__device__ __align__(1024) bf16 g_xt   [(size_t)NB * LSEQ * HDIM];
__device__ __align__(1024) bf16 g_xph  [(size_t)NB * LSEQ * HDIM];
__device__ __align__(1024) bf16 g_xpsi [(size_t)NB * LSEQ * HDIM];
__device__ __align__(1024) bf16 g_xpsiT[(size_t)NB * HDIM * LSEQ];
__device__ __align__(1024) float g_S   [(size_t)NB * LSEQ * LSEQ]; // fp32 logits
__device__ __align__(1024) bf16 g_P    [(size_t)NB * LSEQ * LSEQ]; // bf16 attention
__device__ __align__(1024) bf16 g_xadd [(size_t)NB * LSEQ * HDIM];
__device__ __align__(1024) bf16 g_h1   [(size_t)NB * LSEQ * CHALF];

#define GEMM_SMEM 66560

// ---------------- common asm helpers ----------------------------------------
__device__ __forceinline__ void cp16(uint32_t dst, const void* src) {
    asm volatile("cp.async.cg.shared.global [%0], [%1], 16;"
                 :: "r"(dst), "l"(src) : "memory");
}
#define CP_COMMIT() asm volatile("cp.async.commit_group;" ::: "memory")
#define CP_WAIT1()  asm volatile("cp.async.wait_group 1;" ::: "memory")
#define CP_WAIT0()  asm volatile("cp.async.wait_group 0;" ::: "memory")

#if !TC05
__device__ __forceinline__ void ldsm4(uint32_t* r, uint32_t addr) {
    asm volatile("ldmatrix.sync.aligned.m8n8.x4.shared.b16 {%0,%1,%2,%3}, [%4];"
                 : "=r"(r[0]), "=r"(r[1]), "=r"(r[2]), "=r"(r[3]) : "r"(addr));
}
__device__ __forceinline__ void mma_bf16(float* c, const uint32_t* a, const uint32_t* b) {
    asm volatile("mma.sync.aligned.m16n8k16.row.col.f32.bf16.bf16.f32 "
                 "{%0,%1,%2,%3},{%4,%5,%6,%7},{%8,%9},{%0,%1,%2,%3};"
                 : "+f"(c[0]), "+f"(c[1]), "+f"(c[2]), "+f"(c[3])
                 : "r"(a[0]), "r"(a[1]), "r"(a[2]), "r"(a[3]), "r"(b[0]), "r"(b[1]));
}
#endif

#if TC05
// SW128 K-major smem descriptor: layout=SW128, version=1, SBO=64, LBO=1
__device__ __forceinline__ uint64_t mkdesc(uint32_t addr) {
    return 0x4000404000010000ULL | ((uint64_t)(addr >> 4) & 0x3FFF);
}
#define IDESC_128x128 0x8200490u
__device__ __forceinline__ void mma_ss(uint32_t d, uint64_t ad, uint64_t bd,
                                       uint32_t idesc, int en) {
    asm volatile(
        "{\n\t.reg .pred p;\n\tsetp.ne.b32 p, %4, 0;\n\t"
        "tcgen05.mma.cta_group::1.kind::f16 [%0], %1, %2, %3, {%5, %5, %5, %5}, p;\n\t}"
        :: "r"(d), "l"(ad), "l"(bd), "r"(idesc), "r"(en), "r"(0) : "memory");
}
#define MBAR_WAIT(addr, ph) do {                                              \
    asm volatile(                                                             \
        "{\n\t.reg .pred P1;\n\t"                                             \
        "W_%=: mbarrier.try_wait.parity.acquire.cta.shared::cta.b64 P1, [%0], %1, 0x989680;\n\t" \
        "@!P1 bra W_%=;\n\t}"                                                 \
        :: "r"(addr), "r"(ph) : "memory");                                    \
} while (0)
#define LDTM_X32(r, a)                                                        \
    asm volatile(                                                             \
        "tcgen05.ld.sync.aligned.32x32b.x32.b32 "                             \
        "{%0,%1,%2,%3,%4,%5,%6,%7,%8,%9,%10,%11,%12,%13,%14,%15,"             \
        "%16,%17,%18,%19,%20,%21,%22,%23,%24,%25,%26,%27,%28,%29,%30,%31}, [%32];" \
        : "=r"((r)[0]),  "=r"((r)[1]),  "=r"((r)[2]),  "=r"((r)[3]),          \
          "=r"((r)[4]),  "=r"((r)[5]),  "=r"((r)[6]),  "=r"((r)[7]),          \
          "=r"((r)[8]),  "=r"((r)[9]),  "=r"((r)[10]), "=r"((r)[11]),         \
          "=r"((r)[12]), "=r"((r)[13]), "=r"((r)[14]), "=r"((r)[15]),         \
          "=r"((r)[16]), "=r"((r)[17]), "=r"((r)[18]), "=r"((r)[19]),         \
          "=r"((r)[20]), "=r"((r)[21]), "=r"((r)[22]), "=r"((r)[23]),         \
          "=r"((r)[24]), "=r"((r)[25]), "=r"((r)[26]), "=r"((r)[27]),         \
          "=r"((r)[28]), "=r"((r)[29]), "=r"((r)[30]), "=r"((r)[31])          \
        : "r"(a))
#define AOFF(b) (1024u + (b) * 16384u)
#define BOFF(b) (33792u + (b) * 16384u)
#endif

// ---------------- universal GEMM ---------------------------------------------
// C[M,N] = A[M,K] @ Bt[N,K]^T, tile 128x128, batch via blockIdx.z.
// EPI: 0 bias->bf16 | 2 fp32 | 3 bf16 | 4 bias+leaky->bf16 | 5 bias+tanh+res->fp32
template <int EPI>
__global__ void __launch_bounds__(256)
gemm5(const bf16* __restrict__ A, const bf16* __restrict__ Bt,
      const float* __restrict__ bias, const float* __restrict__ res,
      void* __restrict__ Cout, int M, int N, int K, long sA, long sB, long sC)
{
    extern __shared__ __align__(1024) char smem[];
    uint32_t sbase = (uint32_t)__cvta_generic_to_shared(smem);
    const int tid = threadIdx.x, wid = tid >> 5, lane = tid & 31;

    A  += (long)blockIdx.z * sA;
    Bt += (long)blockIdx.z * sB;
    const int m0 = blockIdx.y * 128, n0 = blockIdx.x * 128;

#if TC05
    // ==================== tcgen05 path (compute_103a pass only) =============
    if (wid == 0)
        asm volatile("tcgen05.alloc.cta_group::1.sync.aligned.shared::cta.b32 [%0], %1;"
                     :: "r"(sbase), "r"(128u) : "memory");
    if (tid == 0)
        asm volatile("mbarrier.init.shared.b64 [%0], 1;" :: "r"(sbase + 8) : "memory");
    __syncthreads();
    uint32_t tmem;
    asm volatile("ld.shared.b32 %0, [%1];" : "=r"(tmem) : "r"(sbase));

    const int KT = K >> 6;
    auto load_tile = [&](uint32_t off, const bf16* p, int r0, int kt) {
#pragma unroll
        for (int s = 0; s < 4; s++) {
            int g = s * 256 + tid;
            int row = g >> 3, seg = g & 7;
            uint32_t b = row * 128 + seg * 16;
            b = b ^ ((b >> 3) & 0x70);
            cp16(sbase + off + b, p + (long)(r0 + row) * K + kt * 64 + seg * 8);
        }
    };

    load_tile(AOFF(0), A, m0, 0);
    load_tile(BOFF(0), Bt, n0, 0);
    CP_COMMIT();
    for (int kt = 0; kt < KT; kt++) {
        const int buf = kt & 1;
        if (kt >= 1) MBAR_WAIT(sbase + 8, (kt - 1) & 1);
        if (kt + 1 < KT) {
            load_tile(AOFF(buf ^ 1), A, m0, kt + 1);
            load_tile(BOFF(buf ^ 1), Bt, n0, kt + 1);
            CP_COMMIT(); CP_WAIT1();
        } else {
            CP_WAIT0();
        }
        asm volatile("fence.proxy.async.shared::cta;" ::: "memory");
        __syncthreads();
        if (tid == 0) {
            uint64_t ad = mkdesc(sbase + AOFF(buf));
            uint64_t bd = mkdesc(sbase + BOFF(buf));
#pragma unroll
            for (int ks = 0; ks < 4; ks++)
                mma_ss(tmem, ad + 2 * ks, bd + 2 * ks, IDESC_128x128, (kt | ks) != 0);
            asm volatile(
                "tcgen05.commit.cta_group::1.mbarrier::arrive::one.shared::cluster.b64 [%0];"
                :: "r"(sbase + 8) : "memory");
        }
    }
    MBAR_WAIT(sbase + 8, (KT - 1) & 1);
    asm volatile("tcgen05.fence::after_thread_sync;" ::: "memory");

    const int row = m0 + (wid & 3) * 32 + lane;
    const int ch0 = (wid >> 2) * 64;
#pragma unroll
    for (int cb = 0; cb < 2; cb++) {
        uint32_t r[32];
        LDTM_X32(r, tmem + ch0 + cb * 32);
        asm volatile("tcgen05.wait::ld.sync.aligned;" ::: "memory");
        const int col = n0 + ch0 + cb * 32;
        float v[32];
#pragma unroll
        for (int c = 0; c < 32; c++) v[c] = __uint_as_float(r[c]);
        if (EPI == 0 || EPI == 4 || EPI == 5)
#pragma unroll
            for (int c = 0; c < 32; c++) v[c] += bias[col + c];
        if (EPI == 4)
#pragma unroll
            for (int c = 0; c < 32; c++) v[c] = fmaxf(v[c], 0.2f * v[c]);
        if (EPI == 5) {
            const float4* R = (const float4*)(res + (long)row * N + col);
#pragma unroll
            for (int q = 0; q < 8; q++) {
                float4 x4 = R[q];
                v[4*q+0] = tanhf(v[4*q+0]) + x4.x;
                v[4*q+1] = tanhf(v[4*q+1]) + x4.y;
                v[4*q+2] = tanhf(v[4*q+2]) + x4.z;
                v[4*q+3] = tanhf(v[4*q+3]) + x4.w;
            }
        }
        if (EPI == 2 || EPI == 5) {
            float* Cf = (float*)Cout + (long)blockIdx.z * sC + (long)row * N + col;
#pragma unroll
            for (int q = 0; q < 8; q++)
                ((float4*)Cf)[q] = make_float4(v[4*q], v[4*q+1], v[4*q+2], v[4*q+3]);
        } else {
            uint32_t h[16];
#pragma unroll
            for (int c = 0; c < 16; c++) {
                __nv_bfloat162 p2 = __floats2bfloat162_rn(v[2*c], v[2*c+1]);
                h[c] = *(uint32_t*)&p2;
            }
            bf16* Cb = (bf16*)Cout + (long)blockIdx.z * sC + (long)row * N + col;
#pragma unroll
            for (int q = 0; q < 4; q++)
                ((uint4*)Cb)[q] = ((uint4*)h)[q];
        }
    }
    __syncthreads();
    if (wid == 0)
        asm volatile("tcgen05.dealloc.cta_group::1.sync.aligned.b32 %0, %1;"
                     :: "r"(tmem), "r"(128u));
#else
    // ==================== bf16 mma.sync fallback (base sm_103) ==============
    // smem: A[2] at 0/10240, B[2] at 20480/30720; rows padded to 40 bf16 (80B).
    const int wm = wid >> 2, wn = wid & 3;        // 2x4 warp grid
    const int m_off = wm * 64, n_off = wn * 32;

    float acc[4][4][4];
#pragma unroll
    for (int i = 0; i < 4; i++)
#pragma unroll
        for (int j = 0; j < 4; j++)
#pragma unroll
            for (int u = 0; u < 4; u++) acc[i][j][u] = 0.f;

    const int KT = K >> 5;
    auto ldA = [&](int kt, int buf) {
#pragma unroll
        for (int s = 0; s < 2; s++) {
            int ch = s * 256 + tid;
            int r = ch >> 2, seg = ch & 3;
            cp16(sbase + buf * 10240u + r * 80u + seg * 16u,
                 A + (long)(m0 + r) * K + kt * 32 + seg * 8);
        }
    };
    auto ldB = [&](int kt, int buf) {
#pragma unroll
        for (int s = 0; s < 2; s++) {
            int ch = s * 256 + tid;
            int r = ch >> 2, seg = ch & 3;
            cp16(sbase + 20480u + buf * 10240u + r * 80u + seg * 16u,
                 Bt + (long)(n0 + r) * K + kt * 32 + seg * 8);
        }
    };

    ldA(0, 0); ldB(0, 0); CP_COMMIT();

    // ldmatrix lane addressing (constant across k-steps)
    const int a_row = m_off + (lane & 15);          // + mt*16
    const int a_kof = (lane >> 4) * 8;
    const int b_row = n_off + (lane & 7) + ((lane >> 4) & 1) * 8;  // + p*16
    const int b_kof = ((lane >> 3) & 1) * 8;

    for (int kt = 0; kt < KT; kt++) {
        const int buf = kt & 1;
        if (kt + 1 < KT) {
            ldA(kt + 1, buf ^ 1); ldB(kt + 1, buf ^ 1);
            CP_COMMIT(); CP_WAIT1();
        } else {
            CP_WAIT0();
        }
        __syncthreads();
        const uint32_t Ab = sbase + buf * 10240u;
        const uint32_t Bb = sbase + 20480u + buf * 10240u;
#pragma unroll
        for (int kk = 0; kk < 32; kk += 16) {
            uint32_t a[4][4], bq[2][4];
#pragma unroll
            for (int mt = 0; mt < 4; mt++)
                ldsm4(a[mt], Ab + ((a_row + mt * 16) * 40 + kk + a_kof) * 2);
#pragma unroll
            for (int p = 0; p < 2; p++)
                ldsm4(bq[p], Bb + ((b_row + p * 16) * 40 + kk + b_kof) * 2);
#pragma unroll
            for (int mt = 0; mt < 4; mt++)
#pragma unroll
                for (int nt = 0; nt < 4; nt++)
                    mma_bf16(acc[mt][nt], a[mt], &bq[nt >> 1][(nt & 1) * 2]);
        }
        __syncthreads();
    }

    // ---- epilogue ----
    const int l4 = lane >> 2, l2 = (lane & 3) * 2;
#pragma unroll
    for (int mt = 0; mt < 4; mt++) {
#pragma unroll
        for (int nt = 0; nt < 4; nt++) {
            int row = m0 + m_off + mt * 16 + l4;
            int col = n0 + n_off + nt * 8 + l2;
            float c0 = acc[mt][nt][0], c1 = acc[mt][nt][1];
            float c2 = acc[mt][nt][2], c3 = acc[mt][nt][3];
            if (EPI == 0 || EPI == 4 || EPI == 5) {
                float b0 = bias[col], b1 = bias[col + 1];
                c0 += b0; c1 += b1; c2 += b0; c3 += b1;
            }
            if (EPI == 4) {
                c0 = fmaxf(c0, 0.2f * c0); c1 = fmaxf(c1, 0.2f * c1);
                c2 = fmaxf(c2, 0.2f * c2); c3 = fmaxf(c3, 0.2f * c3);
            }
            if (EPI == 5) {
                const float2 r0 = *(const float2*)(res + (long)row * N + col);
                const float2 r1 = *(const float2*)(res + (long)(row + 8) * N + col);
                c0 = tanhf(c0) + r0.x; c1 = tanhf(c1) + r0.y;
                c2 = tanhf(c2) + r1.x; c3 = tanhf(c3) + r1.y;
            }
            if (EPI == 2 || EPI == 5) {
                float* Cf = (float*)Cout + (long)blockIdx.z * sC;
                *(float2*)(Cf + (long)row * N + col)       = make_float2(c0, c1);
                *(float2*)(Cf + (long)(row + 8) * N + col) = make_float2(c2, c3);
            } else {
                bf16* Cb = (bf16*)Cout + (long)blockIdx.z * sC;
                __nv_bfloat162 p0 = __floats2bfloat162_rn(c0, c1);
                __nv_bfloat162 p1 = __floats2bfloat162_rn(c2, c3);
                *(__nv_bfloat162*)(Cb + (long)row * N + col)       = p0;
                *(__nv_bfloat162*)(Cb + (long)(row + 8) * N + col) = p1;
            }
        }
    }
#endif
}

// ---------------- softmax: fp32 in -> bf16 out ------------------------------
__global__ void __launch_bounds__(256)
softmax_k(const float* __restrict__ S, bf16* __restrict__ P)
{
    long base = (long)blockIdx.x * LSEQ;
    const float4* S4 = (const float4*)(S + base);
    int tid = threadIdx.x;
    __shared__ float red[256];

    float4 v0 = S4[tid], v1 = S4[tid + 256];
    float m = fmaxf(fmaxf(fmaxf(v0.x, v0.y), fmaxf(v0.z, v0.w)),
                    fmaxf(fmaxf(v1.x, v1.y), fmaxf(v1.z, v1.w)));
    red[tid] = m;
    __syncthreads();
    for (int s = 128; s > 0; s >>= 1) {
        if (tid < s) red[tid] = fmaxf(red[tid], red[tid + s]);
        __syncthreads();
    }
    m = red[0];
    __syncthreads();

    v0.x = __expf(v0.x - m); v0.y = __expf(v0.y - m);
    v0.z = __expf(v0.z - m); v0.w = __expf(v0.w - m);
    v1.x = __expf(v1.x - m); v1.y = __expf(v1.y - m);
    v1.z = __expf(v1.z - m); v1.w = __expf(v1.w - m);
    float sum = (v0.x + v0.y + v0.z + v0.w) + (v1.x + v1.y + v1.z + v1.w);
    red[tid] = sum;
    __syncthreads();
    for (int s = 128; s > 0; s >>= 1) {
        if (tid < s) red[tid] += red[tid + s];
        __syncthreads();
    }
    float inv = 1.f / red[0];

    uint2* P2 = (uint2*)(P + base);
    __nv_bfloat162 a0 = __floats2bfloat162_rn(v0.x * inv, v0.y * inv);
    __nv_bfloat162 a1 = __floats2bfloat162_rn(v0.z * inv, v0.w * inv);
    __nv_bfloat162 b0 = __floats2bfloat162_rn(v1.x * inv, v1.y * inv);
    __nv_bfloat162 b1 = __floats2bfloat162_rn(v1.z * inv, v1.w * inv);
    P2[tid]       = make_uint2(*(uint32_t*)&a0, *(uint32_t*)&a1);
    P2[tid + 256] = make_uint2(*(uint32_t*)&b0, *(uint32_t*)&b1);
}

// ---------------- conversions / transposes ----------------------------------
__global__ void __launch_bounds__(256)
f2b_k(const float* __restrict__ in, bf16* __restrict__ out, int n4)
{
    int i = blockIdx.x * 256 + threadIdx.x;
    if (i < n4) {
        float4 v = ((const float4*)in)[i];
        ((__nv_bfloat162*)out)[2 * i]     = __floats2bfloat162_rn(v.x, v.y);
        ((__nv_bfloat162*)out)[2 * i + 1] = __floats2bfloat162_rn(v.z, v.w);
    }
}

// fp32 [Kd, Nd] -> bf16 [Nd, Kd]
__global__ void wT_k(const float* __restrict__ in, bf16* __restrict__ out,
                     int Kd, int Nd)
{
    __shared__ float t[32][33];
    int k0 = blockIdx.y * 32, n0 = blockIdx.x * 32;
    int tx = threadIdx.x, ty = threadIdx.y;
#pragma unroll
    for (int i = 0; i < 32; i += 8)
        t[ty + i][tx] = in[(long)(k0 + ty + i) * Nd + n0 + tx];
    __syncthreads();
#pragma unroll
    for (int i = 0; i < 32; i += 8)
        out[(long)(n0 + ty + i) * Kd + k0 + tx] = __float2bfloat16(t[tx][ty + i]);
}

// bf16 [L, H] -> bf16 [H, L] per batch
__global__ void bT_k(const bf16* __restrict__ in, bf16* __restrict__ out)
{
    __shared__ bf16 t[32][33];
    long boff = (long)blockIdx.z * LSEQ * HDIM;
    int l0 = blockIdx.y * 32, h0 = blockIdx.x * 32;
    int tx = threadIdx.x, ty = threadIdx.y;
#pragma unroll
    for (int i = 0; i < 32; i += 8)
        t[ty + i][tx] = in[boff + (long)(l0 + ty + i) * HDIM + h0 + tx];
    __syncthreads();
#pragma unroll
    for (int i = 0; i < 32; i += 8)
        out[boff + (long)(h0 + ty + i) * LSEQ + l0 + tx] = t[tx][ty + i];
}

// ---------------- launch ----------------------------------------------------
extern "C" void kernel_launch(void* const* d_in, const int* in_sizes, int n_in,
                              void* d_out, int out_size)
{
    const float* x   = (const float*)d_in[0];
    const float* thw = (const float*)d_in[1];
    const float* thb = (const float*)d_in[2];
    const float* phw = (const float*)d_in[3];
    const float* phb = (const float*)d_in[4];
    const float* psw = (const float*)d_in[5];
    const float* psb = (const float*)d_in[6];
    const float* r1w = (const float*)d_in[7];
    const float* r1b = (const float*)d_in[8];
    const float* r2w = (const float*)d_in[9];
    const float* r2b = (const float*)d_in[10];
    float* out = (float*)d_out;

    bf16 *p_xb, *p_wthT, *p_wphT, *p_wpsT, *p_wr1T, *p_wr2T;
    bf16 *p_xt, *p_xph, *p_xpsi, *p_xpsiT, *p_P, *p_xadd, *p_h1;
    float *p_S;
    cudaGetSymbolAddress((void**)&p_xb,    g_xb);
    cudaGetSymbolAddress((void**)&p_wthT,  g_wthT);
    cudaGetSymbolAddress((void**)&p_wphT,  g_wphT);
    cudaGetSymbolAddress((void**)&p_wpsT,  g_wpsT);
    cudaGetSymbolAddress((void**)&p_wr1T,  g_wr1T);
    cudaGetSymbolAddress((void**)&p_wr2T,  g_wr2T);
    cudaGetSymbolAddress((void**)&p_xt,    g_xt);
    cudaGetSymbolAddress((void**)&p_xph,   g_xph);
    cudaGetSymbolAddress((void**)&p_xpsi,  g_xpsi);
    cudaGetSymbolAddress((void**)&p_xpsiT, g_xpsiT);
    cudaGetSymbolAddress((void**)&p_S,     g_S);
    cudaGetSymbolAddress((void**)&p_P,     g_P);
    cudaGetSymbolAddress((void**)&p_xadd,  g_xadd);
    cudaGetSymbolAddress((void**)&p_h1,    g_h1);

    cudaFuncSetAttribute(gemm5<0>, cudaFuncAttributeMaxDynamicSharedMemorySize, GEMM_SMEM);
    cudaFuncSetAttribute(gemm5<2>, cudaFuncAttributeMaxDynamicSharedMemorySize, GEMM_SMEM);
    cudaFuncSetAttribute(gemm5<3>, cudaFuncAttributeMaxDynamicSharedMemorySize, GEMM_SMEM);
    cudaFuncSetAttribute(gemm5<4>, cudaFuncAttributeMaxDynamicSharedMemorySize, GEMM_SMEM);
    cudaFuncSetAttribute(gemm5<5>, cudaFuncAttributeMaxDynamicSharedMemorySize, GEMM_SMEM);

    const int M = NB * LSEQ;                 // 16384
    const long sLH = (long)LSEQ * HDIM;
    const long sLL = (long)LSEQ * LSEQ;

    // 0) convert inputs
    f2b_k<<<(M * CDIM / 4 + 255) / 256, 256>>>(x, p_xb, M * CDIM / 4);
    {
        dim3 b(32, 8);
        wT_k<<<dim3(HDIM / 32, CDIM / 32), b>>>(thw, p_wthT, CDIM, HDIM);
        wT_k<<<dim3(HDIM / 32, CDIM / 32), b>>>(phw, p_wphT, CDIM, HDIM);
        wT_k<<<dim3(HDIM / 32, CDIM / 32), b>>>(psw, p_wpsT, CDIM, HDIM);
        wT_k<<<dim3(CHALF / 32, HDIM / 32), b>>>(r1w, p_wr1T, HDIM, CHALF);
        wT_k<<<dim3(CDIM / 32, CHALF / 32), b>>>(r2w, p_wr2T, CHALF, CDIM);
    }

    // 1) projections
    {
        dim3 g(HDIM / 128, M / 128, 1);
        gemm5<0><<<g, 256, GEMM_SMEM>>>(p_xb, p_wthT, thb, nullptr, p_xt,
                                        M, HDIM, CDIM, 0, 0, 0);
        gemm5<0><<<g, 256, GEMM_SMEM>>>(p_xb, p_wphT, phb, nullptr, p_xph,
                                        M, HDIM, CDIM, 0, 0, 0);
        gemm5<0><<<g, 256, GEMM_SMEM>>>(p_xb, p_wpsT, psb, nullptr, p_xpsi,
                                        M, HDIM, CDIM, 0, 0, 0);
    }

    // 1b) transpose psi per batch -> [H, L]
    bT_k<<<dim3(HDIM / 32, LSEQ / 32, NB), dim3(32, 8)>>>(p_xpsi, p_xpsiT);

    // 2) logits (fp32 out)
    gemm5<2><<<dim3(LSEQ / 128, LSEQ / 128, NB), 256, GEMM_SMEM>>>(
        p_xph, p_xt, nullptr, nullptr, p_S, LSEQ, LSEQ, HDIM, sLH, sLH, sLL);

    // 3) softmax -> bf16 P
    softmax_k<<<NB * LSEQ, 256>>>(p_S, p_P);

    // 4) x_add = P @ x_psi  (B = x_psi^T [H, L])
    gemm5<3><<<dim3(HDIM / 128, LSEQ / 128, NB), 256, GEMM_SMEM>>>(
        p_P, p_xpsiT, nullptr, nullptr, p_xadd, LSEQ, HDIM, LSEQ, sLL, sLH, sLH);

    // 5) h1 = leaky_relu(x_add @ r1w + r1b)
    gemm5<4><<<dim3(CHALF / 128, M / 128, 1), 256, GEMM_SMEM>>>(
        p_xadd, p_wr1T, r1b, nullptr, p_h1, M, CHALF, HDIM, 0, 0, 0);

    // 6) out = x + tanh(h1 @ r2w + r2b)
    gemm5<5><<<dim3(CDIM / 128, M / 128, 1), 256, GEMM_SMEM>>>(
        p_h1, p_wr2T, r2b, x, out, M, CDIM, CHALF, 0, 0, 0);
}